// round 4
// baseline (speedup 1.0000x reference)
#include <cuda_runtime.h>

#define NB 16
#define NF 6
#define NPIX 262144
#define NK 8
#define NITERS 12
#define BPB 32          // blocks per batch in pass kernels
#define SPLIT 8         // blocks per (b,f) in stats kernel
#define NSLOT 56        // NK*(NF+1) partial-sum slots

// Scratch (static __device__ — no allocations allowed)
__device__ float d_statpart[NB * NF * SPLIT * 2];
__device__ float d_mean[NB * NF];
__device__ float d_sinv[NB * NF];
__device__ float d_g[NB * NK * NF];   // folded centroid weights: 2*alpha*s_f*c_kf
__device__ float d_h[NB * NK];        // folded centroid bias
__device__ float d_part[NB * BPB * NSLOT];

__device__ __forceinline__ float ex2f(float x) {
    float y; asm("ex2.approx.ftz.f32 %0, %1;" : "=f"(y) : "f"(x)); return y;
}
__device__ __forceinline__ float rcpf(float x) {
    float y; asm("rcp.approx.ftz.f32 %0, %1;" : "=f"(y) : "f"(x)); return y;
}

// ---------------------------------------------------------------------------
// Per-(b,f) sum / sumsq partials over pixels
// ---------------------------------------------------------------------------
__global__ __launch_bounds__(256) void stats_kernel(const float* __restrict__ feat) {
    int bf = blockIdx.x >> 3;     // / SPLIT
    int part = blockIdx.x & 7;    // % SPLIT
    const float4* p = ((const float4*)feat) + (size_t)bf * (NPIX / 4);
    int t = threadIdx.x;
    float s = 0.f, q = 0.f;
    #pragma unroll 8
    for (int i = 0; i < 32; i++) {
        float4 v = p[part * 8192 + i * 256 + t];
        s += (v.x + v.y) + (v.z + v.w);
        q = fmaf(v.x, v.x, q); q = fmaf(v.y, v.y, q);
        q = fmaf(v.z, v.z, q); q = fmaf(v.w, v.w, q);
    }
    #pragma unroll
    for (int o = 16; o; o >>= 1) {
        s += __shfl_xor_sync(0xffffffffu, s, o);
        q += __shfl_xor_sync(0xffffffffu, q, o);
    }
    __shared__ float sm[16];
    if ((t & 31) == 0) { sm[t >> 5] = s; sm[8 + (t >> 5)] = q; }
    __syncthreads();
    if (t == 0) {
        float S = 0.f, Q = 0.f;
        #pragma unroll
        for (int i = 0; i < 8; i++) { S += sm[i]; Q += sm[8 + i]; }
        d_statpart[(bf * SPLIT + part) * 2 + 0] = S;
        d_statpart[(bf * SPLIT + part) * 2 + 1] = Q;
    }
}

// ---------------------------------------------------------------------------
// Finalize mean/invstd; gather initial centroids; fold into (g, h)
// logit_k(pixel) = sum_f u_f * g_kf + h_k   (softmax shift-invariance used to
// drop the per-pixel x2/T term; log2e folded so exp is a single MUFU ex2)
// ---------------------------------------------------------------------------
__global__ void init_kernel(const float* __restrict__ feat, const int* __restrict__ idx) {
    int t = threadIdx.x;  // 128 = NB*NK
    if (t < NB * NF) {
        float S = 0.f, Q = 0.f;
        for (int i = 0; i < SPLIT; i++) {
            S += d_statpart[(t * SPLIT + i) * 2 + 0];
            Q += d_statpart[(t * SPLIT + i) * 2 + 1];
        }
        float mean = S * (1.f / (float)NPIX);
        float var = (Q - (float)NPIX * mean * mean) * (1.f / (float)(NPIX - 1));
        var = fmaxf(var, 0.f);
        float sd = sqrtf(var);
        d_mean[t] = mean;
        d_sinv[t] = 1.f / fmaxf(sd, 1e-6f);
    }
    __syncthreads();
    int b = t >> 3;
    int n = idx[t];
    const float alpha = 1.4426950408889634f / 0.15f;  // log2(e)/TEMP
    float c2 = 0.f;
    float g[NF];
    #pragma unroll
    for (int f = 0; f < NF; f++) {
        float u = feat[(size_t)(b * NF + f) * NPIX + n];
        float c = (u - d_mean[b * NF + f]) * d_sinv[b * NF + f];
        c2 = fmaf(c, c, c2);
        g[f] = 2.f * alpha * d_sinv[b * NF + f] * c;
    }
    float h = -alpha * c2;
    #pragma unroll
    for (int f = 0; f < NF; f++) {
        h -= d_mean[b * NF + f] * g[f];
        d_g[t * NF + f] = g[f];
    }
    d_h[t] = h;
}

// ---------------------------------------------------------------------------
// Main accumulation pass: softmax assignment + accumulate (W, A) partials
// ---------------------------------------------------------------------------
__global__ __launch_bounds__(256, 1) void pass_acc_kernel(const float* __restrict__ feat) {
    int b = blockIdx.x >> 5;   // / BPB
    int blk = blockIdx.x & 31; // % BPB
    int t = threadIdx.x;

    float g[NK][NF], h[NK];
    #pragma unroll
    for (int k = 0; k < NK; k++) {
        h[k] = d_h[b * NK + k];
        #pragma unroll
        for (int f = 0; f < NF; f++) g[k][f] = d_g[(b * NK + k) * NF + f];
    }
    float aW[NK];
    float aA[NK][NF];
    #pragma unroll
    for (int k = 0; k < NK; k++) {
        aW[k] = 0.f;
        #pragma unroll
        for (int f = 0; f < NF; f++) aA[k][f] = 0.f;
    }

    const float* base = feat + (size_t)b * NF * NPIX;
    #pragma unroll
    for (int it = 0; it < 8; it++) {
        int n4 = blk * 256 + t + it * 8192;
        float4 u[NF];
        #pragma unroll
        for (int f = 0; f < NF; f++)
            u[f] = ((const float4*)(base + (size_t)f * NPIX))[n4];
        #pragma unroll
        for (int j = 0; j < 4; j++) {
            float x[NF];
            #pragma unroll
            for (int f = 0; f < NF; f++)
                x[f] = (j == 0) ? u[f].x : ((j == 1) ? u[f].y : ((j == 2) ? u[f].z : u[f].w));
            float l[NK];
            #pragma unroll
            for (int k = 0; k < NK; k++) {
                float a = h[k];
                #pragma unroll
                for (int f = 0; f < NF; f++) a = fmaf(x[f], g[k][f], a);
                l[k] = a;
            }
            float m = l[0];
            #pragma unroll
            for (int k = 1; k < NK; k++) m = fmaxf(m, l[k]);
            float p[NK]; float s = 0.f;
            #pragma unroll
            for (int k = 0; k < NK; k++) { p[k] = ex2f(l[k] - m); s += p[k]; }
            float r = rcpf(s);
            float xr[NF];
            #pragma unroll
            for (int f = 0; f < NF; f++) xr[f] = x[f] * r;
            #pragma unroll
            for (int k = 0; k < NK; k++) {
                aW[k] = fmaf(p[k], r, aW[k]);
                #pragma unroll
                for (int f = 0; f < NF; f++) aA[k][f] = fmaf(p[k], xr[f], aA[k][f]);
            }
        }
    }

    // Deterministic block reduction: warp shfl -> smem per-warp -> fixed-order sum
    __shared__ float sm[8][NSLOT];
    int w = t >> 5, lane = t & 31;
    #pragma unroll
    for (int k = 0; k < NK; k++) {
        #pragma unroll
        for (int f = 0; f < NF; f++) {
            float v = aA[k][f];
            #pragma unroll
            for (int o = 16; o; o >>= 1) v += __shfl_xor_sync(0xffffffffu, v, o);
            if (lane == 0) sm[w][k * NF + f] = v;
        }
        float v = aW[k];
        #pragma unroll
        for (int o = 16; o; o >>= 1) v += __shfl_xor_sync(0xffffffffu, v, o);
        if (lane == 0) sm[w][48 + k] = v;
    }
    __syncthreads();
    if (t < NSLOT) {
        float v = 0.f;
        #pragma unroll
        for (int i = 0; i < 8; i++) v += sm[i][t];
        d_part[(size_t)(b * BPB + blk) * NSLOT + t] = v;
    }
}

// ---------------------------------------------------------------------------
// Centroid update in raw-u space, refold into (g, h); fixed reduction order
// ---------------------------------------------------------------------------
__global__ void update_kernel() {
    int t = threadIdx.x;  // 128 = NB*NK
    int b = t >> 3, k = t & 7;
    float W = 0.f;
    float A[NF] = {0.f, 0.f, 0.f, 0.f, 0.f, 0.f};
    for (int blk = 0; blk < BPB; blk++) {
        const float* pp = d_part + (size_t)(b * BPB + blk) * NSLOT;
        W += pp[48 + k];
        #pragma unroll
        for (int f = 0; f < NF; f++) A[f] += pp[k * NF + f];
    }
    float Wc = fmaxf(W, 1e-6f);
    float rW = 1.f / Wc;
    const float alpha = 1.4426950408889634f / 0.15f;
    float c2 = 0.f;
    float g[NF];
    #pragma unroll
    for (int f = 0; f < NF; f++) {
        // C_kf = s_f * (A_f - m_f*W) / clip(W, EPS)   (matches reference exactly)
        float c = d_sinv[b * NF + f] * (A[f] - d_mean[b * NF + f] * W) * rW;
        c2 = fmaf(c, c, c2);
        g[f] = 2.f * alpha * d_sinv[b * NF + f] * c;
    }
    float h = -alpha * c2;
    #pragma unroll
    for (int f = 0; f < NF; f++) {
        h -= d_mean[b * NF + f] * g[f];
        d_g[t * NF + f] = g[f];
    }
    d_h[t] = h;
}

// ---------------------------------------------------------------------------
// Final pass: compute S from C_11 and write output (no accumulation)
// ---------------------------------------------------------------------------
__global__ __launch_bounds__(256, 1) void pass_out_kernel(const float* __restrict__ feat,
                                                          float* __restrict__ out) {
    int b = blockIdx.x >> 5;
    int blk = blockIdx.x & 31;
    int t = threadIdx.x;

    float g[NK][NF], h[NK];
    #pragma unroll
    for (int k = 0; k < NK; k++) {
        h[k] = d_h[b * NK + k];
        #pragma unroll
        for (int f = 0; f < NF; f++) g[k][f] = d_g[(b * NK + k) * NF + f];
    }
    const float* base = feat + (size_t)b * NF * NPIX;
    #pragma unroll
    for (int it = 0; it < 8; it++) {
        int n4 = blk * 256 + t + it * 8192;
        float4 u[NF];
        #pragma unroll
        for (int f = 0; f < NF; f++)
            u[f] = ((const float4*)(base + (size_t)f * NPIX))[n4];
        float wv[NK][4];
        #pragma unroll
        for (int j = 0; j < 4; j++) {
            float x[NF];
            #pragma unroll
            for (int f = 0; f < NF; f++)
                x[f] = (j == 0) ? u[f].x : ((j == 1) ? u[f].y : ((j == 2) ? u[f].z : u[f].w));
            float l[NK];
            #pragma unroll
            for (int k = 0; k < NK; k++) {
                float a = h[k];
                #pragma unroll
                for (int f = 0; f < NF; f++) a = fmaf(x[f], g[k][f], a);
                l[k] = a;
            }
            float m = l[0];
            #pragma unroll
            for (int k = 1; k < NK; k++) m = fmaxf(m, l[k]);
            float p[NK]; float s = 0.f;
            #pragma unroll
            for (int k = 0; k < NK; k++) { p[k] = ex2f(l[k] - m); s += p[k]; }
            float r = rcpf(s);
            #pragma unroll
            for (int k = 0; k < NK; k++) wv[k][j] = p[k] * r;
        }
        #pragma unroll
        for (int k = 0; k < NK; k++) {
            float4 o4 = make_float4(wv[k][0], wv[k][1], wv[k][2], wv[k][3]);
            ((float4*)(out + (size_t)(b * NK + k) * NPIX))[n4] = o4;
        }
    }
}

extern "C" void kernel_launch(void* const* d_in, const int* in_sizes, int n_in,
                              void* d_out, int out_size) {
    const float* feat = (const float*)d_in[0];
    const int* idx = (const int*)d_in[1];
    float* out = (float*)d_out;

    stats_kernel<<<NB * NF * SPLIT, 256>>>(feat);
    init_kernel<<<1, 128>>>(feat, idx);
    for (int i = 0; i < NITERS - 1; i++) {
        pass_acc_kernel<<<NB * BPB, 256>>>(feat);
        update_kernel<<<1, 128>>>();
    }
    pass_out_kernel<<<NB * BPB, 256>>>(feat, out);
}

// round 5
// speedup vs baseline: 1.2851x; 1.2851x over previous
#include <cuda_runtime.h>

#define NB 16
#define NF 6
#define NPIX 262144
#define NK 8
#define NKK 4          // packed k-pairs
#define NITERS 12
#define BPB 8          // blocks per batch in pass kernels (grid = 128 = single wave)
#define SPLIT 8        // blocks per (b,f) in stats kernel
#define NSLOT 56       // NK*(NF+1) partial-sum slots

typedef unsigned long long u64p;   // packed f32x2

// Scratch (static __device__ — no allocations allowed)
__device__ float d_statpart[NB * NF * SPLIT * 2];
__device__ float d_mean[NB * NF];
__device__ float d_sinv[NB * NF];
__device__ float d_g[NB * NK * NF];   // folded centroid weights (init only)
__device__ float d_h[NB * NK];        // folded centroid bias   (init only)
__device__ float d_part[NB * BPB * NSLOT];

__device__ __forceinline__ float ex2f(float x) {
    float y; asm("ex2.approx.ftz.f32 %0, %1;" : "=f"(y) : "f"(x)); return y;
}
__device__ __forceinline__ float rcpf(float x) {
    float y; asm("rcp.approx.ftz.f32 %0, %1;" : "=f"(y) : "f"(x)); return y;
}
// ---- packed f32x2 helpers (FFMA2 etc — only reachable via PTX) ----
__device__ __forceinline__ u64p pk2(float lo, float hi) {
    u64p r; asm("mov.b64 %0, {%1, %2};" : "=l"(r) : "f"(lo), "f"(hi)); return r;
}
__device__ __forceinline__ void upk2(u64p v, float& lo, float& hi) {
    asm("mov.b64 {%0, %1}, %2;" : "=f"(lo), "=f"(hi) : "l"(v));
}
__device__ __forceinline__ u64p fma2(u64p a, u64p b, u64p c) {
    u64p d; asm("fma.rn.f32x2 %0, %1, %2, %3;" : "=l"(d) : "l"(a), "l"(b), "l"(c)); return d;
}
__device__ __forceinline__ u64p add2(u64p a, u64p b) {
    u64p d; asm("add.rn.f32x2 %0, %1, %2;" : "=l"(d) : "l"(a), "l"(b)); return d;
}
__device__ __forceinline__ u64p mul2(u64p a, u64p b) {
    u64p d; asm("mul.rn.f32x2 %0, %1, %2;" : "=l"(d) : "l"(a), "l"(b)); return d;
}

// ---------------------------------------------------------------------------
// Per-(b,f) sum / sumsq partials over pixels
// ---------------------------------------------------------------------------
__global__ __launch_bounds__(256) void stats_kernel(const float* __restrict__ feat) {
    int bf = blockIdx.x >> 3;     // / SPLIT
    int part = blockIdx.x & 7;    // % SPLIT
    const float4* p = ((const float4*)feat) + (size_t)bf * (NPIX / 4);
    int t = threadIdx.x;
    float s = 0.f, q = 0.f;
    #pragma unroll 8
    for (int i = 0; i < 32; i++) {
        float4 v = p[part * 8192 + i * 256 + t];
        s += (v.x + v.y) + (v.z + v.w);
        q = fmaf(v.x, v.x, q); q = fmaf(v.y, v.y, q);
        q = fmaf(v.z, v.z, q); q = fmaf(v.w, v.w, q);
    }
    #pragma unroll
    for (int o = 16; o; o >>= 1) {
        s += __shfl_xor_sync(0xffffffffu, s, o);
        q += __shfl_xor_sync(0xffffffffu, q, o);
    }
    __shared__ float sm[16];
    if ((t & 31) == 0) { sm[t >> 5] = s; sm[8 + (t >> 5)] = q; }
    __syncthreads();
    if (t == 0) {
        float S = 0.f, Q = 0.f;
        #pragma unroll
        for (int i = 0; i < 8; i++) { S += sm[i]; Q += sm[8 + i]; }
        d_statpart[(bf * SPLIT + part) * 2 + 0] = S;
        d_statpart[(bf * SPLIT + part) * 2 + 1] = Q;
    }
}

// ---------------------------------------------------------------------------
// Finalize mean/invstd; gather initial centroids; fold into (g, h)
// logit_k(pixel) = sum_f u_f * g_kf + h_k   (softmax shift-invariance drops the
// per-pixel x2/T term; log2e folded so exp is a single MUFU ex2)
// ---------------------------------------------------------------------------
__global__ void init_kernel(const float* __restrict__ feat, const int* __restrict__ idx) {
    int t = threadIdx.x;  // 128 = NB*NK
    if (t < NB * NF) {
        float S = 0.f, Q = 0.f;
        for (int i = 0; i < SPLIT; i++) {
            S += d_statpart[(t * SPLIT + i) * 2 + 0];
            Q += d_statpart[(t * SPLIT + i) * 2 + 1];
        }
        float mean = S * (1.f / (float)NPIX);
        float var = (Q - (float)NPIX * mean * mean) * (1.f / (float)(NPIX - 1));
        var = fmaxf(var, 0.f);
        float sd = sqrtf(var);
        d_mean[t] = mean;
        d_sinv[t] = 1.f / fmaxf(sd, 1e-6f);
    }
    __syncthreads();
    int b = t >> 3;
    int n = idx[t];
    const float alpha = 1.4426950408889634f / 0.15f;  // log2(e)/TEMP
    float c2 = 0.f;
    float g[NF];
    #pragma unroll
    for (int f = 0; f < NF; f++) {
        float u = feat[(size_t)(b * NF + f) * NPIX + n];
        float c = (u - d_mean[b * NF + f]) * d_sinv[b * NF + f];
        c2 = fmaf(c, c, c2);
        g[f] = 2.f * alpha * d_sinv[b * NF + f] * c;
    }
    float h = -alpha * c2;
    #pragma unroll
    for (int f = 0; f < NF; f++) {
        h -= d_mean[b * NF + f] * g[f];
        d_g[t * NF + f] = g[f];
    }
    d_h[t] = h;
}

// ---------------------------------------------------------------------------
// Per-block preamble: compute this batch's centroid update from the previous
// pass's partials (redundantly per block — launch boundary is the grid sync),
// or load the init g/h on the first pass. Result in shared.
// ---------------------------------------------------------------------------
__device__ __forceinline__ void compute_gh(int b, int do_update,
                                           float* s_g, float* s_h) {
    int t = threadIdx.x;
    if (t < NK) {
        int k = t;
        float gg[NF], hh;
        if (do_update) {
            float W = 0.f, A[NF] = {0.f, 0.f, 0.f, 0.f, 0.f, 0.f};
            for (int i = 0; i < BPB; i++) {
                const float* pp = d_part + (size_t)(b * BPB + i) * NSLOT;
                W += pp[48 + k];
                #pragma unroll
                for (int f = 0; f < NF; f++) A[f] += pp[k * NF + f];
            }
            float rW = 1.f / fmaxf(W, 1e-6f);
            const float alpha = 1.4426950408889634f / 0.15f;
            float c2 = 0.f;
            #pragma unroll
            for (int f = 0; f < NF; f++) {
                float si = d_sinv[b * NF + f];
                // C_kf = s_f * (A_f - m_f*W) / clip(W, EPS)  (matches reference)
                float c = si * (A[f] - d_mean[b * NF + f] * W) * rW;
                c2 = fmaf(c, c, c2);
                gg[f] = 2.f * alpha * si * c;
            }
            hh = -alpha * c2;
            #pragma unroll
            for (int f = 0; f < NF; f++) hh -= d_mean[b * NF + f] * gg[f];
        } else {
            #pragma unroll
            for (int f = 0; f < NF; f++) gg[f] = d_g[(b * NK + k) * NF + f];
            hh = d_h[b * NK + k];
        }
        #pragma unroll
        for (int f = 0; f < NF; f++) s_g[k * NF + f] = gg[f];
        s_h[k] = hh;
    }
}

// ---------------------------------------------------------------------------
// Packed softmax core: given x[6] and packed g2/h2, produce packed p2 (exp)
// and scalar r = 1/sum. All f32x2 math is IEEE rn — identical to scalar.
// ---------------------------------------------------------------------------
__device__ __forceinline__ void softmax_core(const float x[NF],
                                             const u64p g2[NKK][NF], const u64p h2[NKK],
                                             u64p x2[NF], u64p p2[NKK], float& r) {
    #pragma unroll
    for (int f = 0; f < NF; f++) x2[f] = pk2(x[f], x[f]);
    u64p l2[NKK];
    #pragma unroll
    for (int kk = 0; kk < NKK; kk++) l2[kk] = fma2(x2[0], g2[kk][0], h2[kk]);
    #pragma unroll
    for (int f = 1; f < NF; f++)
        #pragma unroll
        for (int kk = 0; kk < NKK; kk++) l2[kk] = fma2(x2[f], g2[kk][f], l2[kk]);
    float l[NK];
    #pragma unroll
    for (int kk = 0; kk < NKK; kk++) upk2(l2[kk], l[2 * kk], l[2 * kk + 1]);
    float m = l[0];
    #pragma unroll
    for (int k = 1; k < NK; k++) m = fmaxf(m, l[k]);
    u64p mn2 = pk2(-m, -m);
    float p[NK];
    #pragma unroll
    for (int kk = 0; kk < NKK; kk++) {
        u64p e = add2(l2[kk], mn2);
        float a, c; upk2(e, a, c);
        p[2 * kk] = ex2f(a);
        p[2 * kk + 1] = ex2f(c);
    }
    #pragma unroll
    for (int kk = 0; kk < NKK; kk++) p2[kk] = pk2(p[2 * kk], p[2 * kk + 1]);
    u64p s2 = add2(add2(p2[0], p2[1]), add2(p2[2], p2[3]));
    float sl, sh; upk2(s2, sl, sh);
    r = rcpf(sl + sh);
}

// ---------------------------------------------------------------------------
// Accumulation pass (self-updating): softmax assignment + accumulate (W, A)
// ---------------------------------------------------------------------------
__global__ __launch_bounds__(256, 1) void pass_acc_kernel(const float* __restrict__ feat,
                                                          int do_update) {
    int b = blockIdx.x >> 3;   // / BPB
    int blk = blockIdx.x & 7;  // % BPB
    int t = threadIdx.x;

    __shared__ float s_g[NK * NF], s_h[NK];
    compute_gh(b, do_update, s_g, s_h);
    __syncthreads();

    u64p g2[NKK][NF], h2[NKK];
    #pragma unroll
    for (int kk = 0; kk < NKK; kk++) {
        h2[kk] = pk2(s_h[2 * kk], s_h[2 * kk + 1]);
        #pragma unroll
        for (int f = 0; f < NF; f++)
            g2[kk][f] = pk2(s_g[(2 * kk) * NF + f], s_g[(2 * kk + 1) * NF + f]);
    }
    u64p aW2[NKK], aA2[NKK][NF];
    #pragma unroll
    for (int kk = 0; kk < NKK; kk++) {
        aW2[kk] = pk2(0.f, 0.f);
        #pragma unroll
        for (int f = 0; f < NF; f++) aA2[kk][f] = pk2(0.f, 0.f);
    }

    const float4* pf = (const float4*)(feat + (size_t)b * NF * NPIX);
    int off = blk * 8192 + t;
    #pragma unroll 2
    for (int it = 0; it < 32; it++) {
        int n4 = off + it * 256;
        float4 u[NF];
        #pragma unroll
        for (int f = 0; f < NF; f++) u[f] = pf[f * (NPIX / 4) + n4];
        #pragma unroll
        for (int j = 0; j < 4; j++) {
            float x[NF];
            #pragma unroll
            for (int f = 0; f < NF; f++)
                x[f] = (j == 0) ? u[f].x : ((j == 1) ? u[f].y : ((j == 2) ? u[f].z : u[f].w));
            u64p x2[NF], p2[NKK]; float r;
            softmax_core(x, g2, h2, x2, p2, r);
            u64p r2 = pk2(r, r);
            #pragma unroll
            for (int kk = 0; kk < NKK; kk++) aW2[kk] = fma2(p2[kk], r2, aW2[kk]);
            u64p xr2[NF];
            #pragma unroll
            for (int f = 0; f < NF; f++) xr2[f] = mul2(x2[f], r2);
            #pragma unroll
            for (int kk = 0; kk < NKK; kk++)
                #pragma unroll
                for (int f = 0; f < NF; f++)
                    aA2[kk][f] = fma2(p2[kk], xr2[f], aA2[kk][f]);
        }
    }

    // Unpack accumulators, then deterministic block reduction
    float aW[NK], aA[NK][NF];
    #pragma unroll
    for (int kk = 0; kk < NKK; kk++) {
        upk2(aW2[kk], aW[2 * kk], aW[2 * kk + 1]);
        #pragma unroll
        for (int f = 0; f < NF; f++)
            upk2(aA2[kk][f], aA[2 * kk][f], aA[2 * kk + 1][f]);
    }
    __shared__ float sm[8][NSLOT];
    int w = t >> 5, lane = t & 31;
    #pragma unroll
    for (int k = 0; k < NK; k++) {
        #pragma unroll
        for (int f = 0; f < NF; f++) {
            float v = aA[k][f];
            #pragma unroll
            for (int o = 16; o; o >>= 1) v += __shfl_xor_sync(0xffffffffu, v, o);
            if (lane == 0) sm[w][k * NF + f] = v;
        }
        float v = aW[k];
        #pragma unroll
        for (int o = 16; o; o >>= 1) v += __shfl_xor_sync(0xffffffffu, v, o);
        if (lane == 0) sm[w][48 + k] = v;
    }
    __syncthreads();
    if (t < NSLOT) {
        float v = 0.f;
        #pragma unroll
        for (int i = 0; i < 8; i++) v += sm[i][t];
        d_part[(size_t)(b * BPB + blk) * NSLOT + t] = v;
    }
}

// ---------------------------------------------------------------------------
// Final pass (self-updating): compute S from C_11 and write output
// ---------------------------------------------------------------------------
__global__ __launch_bounds__(256, 1) void pass_out_kernel(const float* __restrict__ feat,
                                                          float* __restrict__ out) {
    int b = blockIdx.x >> 3;
    int blk = blockIdx.x & 7;
    int t = threadIdx.x;

    __shared__ float s_g[NK * NF], s_h[NK];
    compute_gh(b, 1, s_g, s_h);
    __syncthreads();

    u64p g2[NKK][NF], h2[NKK];
    #pragma unroll
    for (int kk = 0; kk < NKK; kk++) {
        h2[kk] = pk2(s_h[2 * kk], s_h[2 * kk + 1]);
        #pragma unroll
        for (int f = 0; f < NF; f++)
            g2[kk][f] = pk2(s_g[(2 * kk) * NF + f], s_g[(2 * kk + 1) * NF + f]);
    }

    const float4* pf = (const float4*)(feat + (size_t)b * NF * NPIX);
    float4* po = (float4*)out + (size_t)b * NK * (NPIX / 4);
    int off = blk * 8192 + t;
    #pragma unroll 2
    for (int it = 0; it < 32; it++) {
        int n4 = off + it * 256;
        float4 u[NF];
        #pragma unroll
        for (int f = 0; f < NF; f++) u[f] = pf[f * (NPIX / 4) + n4];
        float wv[NK][4];
        #pragma unroll
        for (int j = 0; j < 4; j++) {
            float x[NF];
            #pragma unroll
            for (int f = 0; f < NF; f++)
                x[f] = (j == 0) ? u[f].x : ((j == 1) ? u[f].y : ((j == 2) ? u[f].z : u[f].w));
            u64p x2[NF], p2[NKK]; float r;
            softmax_core(x, g2, h2, x2, p2, r);
            u64p r2 = pk2(r, r);
            #pragma unroll
            for (int kk = 0; kk < NKK; kk++) {
                u64p w2 = mul2(p2[kk], r2);
                upk2(w2, wv[2 * kk][j], wv[2 * kk + 1][j]);
            }
        }
        #pragma unroll
        for (int k = 0; k < NK; k++) {
            float4 o4 = make_float4(wv[k][0], wv[k][1], wv[k][2], wv[k][3]);
            __stcs(po + k * (NPIX / 4) + n4, o4);   // streaming: don't thrash feat in L2
        }
    }
}

extern "C" void kernel_launch(void* const* d_in, const int* in_sizes, int n_in,
                              void* d_out, int out_size) {
    const float* feat = (const float*)d_in[0];
    const int* idx = (const int*)d_in[1];
    float* out = (float*)d_out;

    stats_kernel<<<NB * NF * SPLIT, 256>>>(feat);
    init_kernel<<<1, 128>>>(feat, idx);
    pass_acc_kernel<<<NB * BPB, 256>>>(feat, 0);          // iter 1: uses init g,h
    for (int i = 1; i < NITERS - 1; i++)
        pass_acc_kernel<<<NB * BPB, 256>>>(feat, 1);      // iters 2..11: self-update
    pass_out_kernel<<<NB * BPB, 256>>>(feat, out);        // iter 12: update + write S
}

// round 7
// speedup vs baseline: 1.6687x; 1.2985x over previous
#include <cuda_runtime.h>
#include <cstdint>

#define NB 16
#define NF 6
#define NPIX 262144
#define NP4 (NPIX / 4)   // 65536 float4 per (b,f)
#define NK 8
#define NKK 4            // packed k-pairs
#define NITERS 12
#define NCH 9            // chunks per batch -> grid 144 (~148 SMs)
#define SPLIT 8          // blocks per (b,f) in stats kernel
#define NSLOT 56         // NK*(NF+1) partial-sum slots
#define STG4 512         // float4s per pipeline stage (per f)
#define NBUF 3           // pipeline depth

typedef unsigned long long u64p;   // packed f32x2 (and cache policy)
typedef unsigned int u32;

// Dynamic smem layout (bytes)
#define BUFB   (NBUF * NF * STG4 * 16)      // 147456
#define MBAR_O (BUFB)                       // 3 mbarriers (24B, pad to 32)
#define GH_O   (BUFB + 32)                  // s_g[48] + s_h[8] floats
#define RED_O  (BUFB + 32 + 224)            // float[8][NSLOT]
#define SMEMSZ (RED_O + 8 * NSLOT * 4)      // ~149.5 KB

// Scratch (static __device__ — no allocations allowed)
__device__ float d_statpart[NB * NF * SPLIT * 2];
__device__ float d_mean[NB * NF];
__device__ float d_sinv[NB * NF];
__device__ float d_g[NB * NK * NF];   // folded centroid weights (init only)
__device__ float d_h[NB * NK];        // folded centroid bias   (init only)
__device__ float d_part[NB * NCH * NSLOT];

__device__ __forceinline__ float ex2f(float x) {
    float y; asm("ex2.approx.ftz.f32 %0, %1;" : "=f"(y) : "f"(x)); return y;
}
__device__ __forceinline__ float rcpf(float x) {
    float y; asm("rcp.approx.ftz.f32 %0, %1;" : "=f"(y) : "f"(x)); return y;
}
// ---- packed f32x2 helpers (FFMA2 etc — only reachable via PTX) ----
__device__ __forceinline__ u64p pk2(float lo, float hi) {
    u64p r; asm("mov.b64 %0, {%1, %2};" : "=l"(r) : "f"(lo), "f"(hi)); return r;
}
__device__ __forceinline__ void upk2(u64p v, float& lo, float& hi) {
    asm("mov.b64 {%0, %1}, %2;" : "=f"(lo), "=f"(hi) : "l"(v));
}
__device__ __forceinline__ u64p fma2(u64p a, u64p b, u64p c) {
    u64p d; asm("fma.rn.f32x2 %0, %1, %2, %3;" : "=l"(d) : "l"(a), "l"(b), "l"(c)); return d;
}
__device__ __forceinline__ u64p add2(u64p a, u64p b) {
    u64p d; asm("add.rn.f32x2 %0, %1, %2;" : "=l"(d) : "l"(a), "l"(b)); return d;
}
__device__ __forceinline__ u64p mul2(u64p a, u64p b) {
    u64p d; asm("mul.rn.f32x2 %0, %1, %2;" : "=l"(d) : "l"(a), "l"(b)); return d;
}
// ---- smem / mbarrier / bulk-copy helpers ----
__device__ __forceinline__ u32 smem_u32(const void* p) {
    u32 a;
    asm("{ .reg .u64 t; cvta.to.shared.u64 t, %1; cvt.u32.u64 %0, t; }" : "=r"(a) : "l"(p));
    return a;
}
__device__ __forceinline__ void mbar_init(u32 mbar, u32 cnt) {
    asm volatile("mbarrier.init.shared.b64 [%0], %1;" :: "r"(mbar), "r"(cnt) : "memory");
}
__device__ __forceinline__ void mbar_expect_tx(u32 mbar, u32 bytes) {
    asm volatile("mbarrier.arrive.expect_tx.shared.b64 _, [%0], %1;" :: "r"(mbar), "r"(bytes) : "memory");
}
__device__ __forceinline__ void mbar_wait(u32 mbar, u32 phase) {
    asm volatile(
        "{\n\t.reg .pred P;\n"
        "WL_%=:\n\t"
        "mbarrier.try_wait.parity.acquire.cta.shared::cta.b64 P, [%0], %1, 0x989680;\n\t"
        "@P bra WD_%=;\n\t"
        "bra WL_%=;\n"
        "WD_%=:\n\t}"
        :: "r"(mbar), "r"(phase) : "memory");
}
__device__ __forceinline__ u64p mk_policy() {
    u64p p; asm("createpolicy.fractional.L2::evict_last.b64 %0, 1.0;" : "=l"(p));
    return p;
}
__device__ __forceinline__ void bulk_g2s(u32 dst, const void* src, u32 bytes,
                                         u32 mbar, u64p pol) {
    asm volatile(
        "cp.async.bulk.shared::cluster.global.mbarrier::complete_tx::bytes.L2::cache_hint "
        "[%0], [%1], %2, [%3], %4;"
        :: "r"(dst), "l"(src), "r"(bytes), "r"(mbar), "l"(pol) : "memory");
}

// ---------------------------------------------------------------------------
// Per-(b,f) sum / sumsq partials over pixels
// ---------------------------------------------------------------------------
__global__ __launch_bounds__(256) void stats_kernel(const float* __restrict__ feat) {
    int bf = blockIdx.x >> 3;     // / SPLIT
    int part = blockIdx.x & 7;    // % SPLIT
    const float4* p = ((const float4*)feat) + (size_t)bf * NP4;
    int t = threadIdx.x;
    float s = 0.f, q = 0.f;
    #pragma unroll 8
    for (int i = 0; i < 32; i++) {
        float4 v = p[part * 8192 + i * 256 + t];
        s += (v.x + v.y) + (v.z + v.w);
        q = fmaf(v.x, v.x, q); q = fmaf(v.y, v.y, q);
        q = fmaf(v.z, v.z, q); q = fmaf(v.w, v.w, q);
    }
    #pragma unroll
    for (int o = 16; o; o >>= 1) {
        s += __shfl_xor_sync(0xffffffffu, s, o);
        q += __shfl_xor_sync(0xffffffffu, q, o);
    }
    __shared__ float sm[16];
    if ((t & 31) == 0) { sm[t >> 5] = s; sm[8 + (t >> 5)] = q; }
    __syncthreads();
    if (t == 0) {
        float S = 0.f, Q = 0.f;
        #pragma unroll
        for (int i = 0; i < 8; i++) { S += sm[i]; Q += sm[8 + i]; }
        d_statpart[(bf * SPLIT + part) * 2 + 0] = S;
        d_statpart[(bf * SPLIT + part) * 2 + 1] = Q;
    }
}

// ---------------------------------------------------------------------------
// Finalize mean/invstd; gather initial centroids; fold into (g, h)
// logit_k(pixel) = sum_f u_f * g_kf + h_k   (softmax shift-invariance drops the
// per-pixel x2/T term; log2e folded so exp is a single MUFU ex2)
// ---------------------------------------------------------------------------
__global__ void init_kernel(const float* __restrict__ feat, const int* __restrict__ idx) {
    int t = threadIdx.x;  // 128 = NB*NK
    if (t < NB * NF) {
        float S = 0.f, Q = 0.f;
        for (int i = 0; i < SPLIT; i++) {
            S += d_statpart[(t * SPLIT + i) * 2 + 0];
            Q += d_statpart[(t * SPLIT + i) * 2 + 1];
        }
        float mean = S * (1.f / (float)NPIX);
        float var = (Q - (float)NPIX * mean * mean) * (1.f / (float)(NPIX - 1));
        var = fmaxf(var, 0.f);
        float sd = sqrtf(var);
        d_mean[t] = mean;
        d_sinv[t] = 1.f / fmaxf(sd, 1e-6f);
    }
    __syncthreads();
    int b = t >> 3;
    int n = idx[t];
    const float alpha = 1.4426950408889634f / 0.15f;  // log2(e)/TEMP
    float c2 = 0.f;
    float g[NF];
    #pragma unroll
    for (int f = 0; f < NF; f++) {
        float u = feat[(size_t)(b * NF + f) * NPIX + n];
        float c = (u - d_mean[b * NF + f]) * d_sinv[b * NF + f];
        c2 = fmaf(c, c, c2);
        g[f] = 2.f * alpha * d_sinv[b * NF + f] * c;
    }
    float h = -alpha * c2;
    #pragma unroll
    for (int f = 0; f < NF; f++) {
        h -= d_mean[b * NF + f] * g[f];
        d_g[t * NF + f] = g[f];
    }
    d_h[t] = h;
}

// ---------------------------------------------------------------------------
// Per-block preamble: centroid update from previous pass's partials
// (redundant per block — the launch boundary is the grid sync).
// ---------------------------------------------------------------------------
__device__ __forceinline__ void compute_gh(int b, int do_update, float* s_g, float* s_h) {
    int t = threadIdx.x;
    if (t < NK) {
        int k = t;
        float gg[NF], hh;
        if (do_update) {
            float W = 0.f, A[NF] = {0.f, 0.f, 0.f, 0.f, 0.f, 0.f};
            for (int i = 0; i < NCH; i++) {
                const float* pp = d_part + (size_t)(b * NCH + i) * NSLOT;
                W += pp[48 + k];
                #pragma unroll
                for (int f = 0; f < NF; f++) A[f] += pp[k * NF + f];
            }
            float rW = 1.f / fmaxf(W, 1e-6f);
            const float alpha = 1.4426950408889634f / 0.15f;
            float c2 = 0.f;
            #pragma unroll
            for (int f = 0; f < NF; f++) {
                float si = d_sinv[b * NF + f];
                // C_kf = s_f * (A_f - m_f*W) / clip(W, EPS)  (matches reference)
                float c = si * (A[f] - d_mean[b * NF + f] * W) * rW;
                c2 = fmaf(c, c, c2);
                gg[f] = 2.f * alpha * si * c;
            }
            hh = -alpha * c2;
            #pragma unroll
            for (int f = 0; f < NF; f++) hh -= d_mean[b * NF + f] * gg[f];
        } else {
            #pragma unroll
            for (int f = 0; f < NF; f++) gg[f] = d_g[(b * NK + k) * NF + f];
            hh = d_h[b * NK + k];
        }
        #pragma unroll
        for (int f = 0; f < NF; f++) s_g[k * NF + f] = gg[f];
        s_h[k] = hh;
    }
}

// ---------------------------------------------------------------------------
// Packed softmax core
// ---------------------------------------------------------------------------
__device__ __forceinline__ void softmax_core(const float x[NF],
                                             const u64p g2[NKK][NF], const u64p h2[NKK],
                                             u64p x2[NF], u64p p2[NKK], float& r) {
    #pragma unroll
    for (int f = 0; f < NF; f++) x2[f] = pk2(x[f], x[f]);
    u64p l2[NKK];
    #pragma unroll
    for (int kk = 0; kk < NKK; kk++) l2[kk] = fma2(x2[0], g2[kk][0], h2[kk]);
    #pragma unroll
    for (int f = 1; f < NF; f++)
        #pragma unroll
        for (int kk = 0; kk < NKK; kk++) l2[kk] = fma2(x2[f], g2[kk][f], l2[kk]);
    float l[NK];
    #pragma unroll
    for (int kk = 0; kk < NKK; kk++) upk2(l2[kk], l[2 * kk], l[2 * kk + 1]);
    float m = l[0];
    #pragma unroll
    for (int k = 1; k < NK; k++) m = fmaxf(m, l[k]);
    u64p mn2 = pk2(-m, -m);
    float p[NK];
    #pragma unroll
    for (int kk = 0; kk < NKK; kk++) {
        u64p e = add2(l2[kk], mn2);
        float a, c; upk2(e, a, c);
        p[2 * kk] = ex2f(a);
        p[2 * kk + 1] = ex2f(c);
    }
    #pragma unroll
    for (int kk = 0; kk < NKK; kk++) p2[kk] = pk2(p[2 * kk], p[2 * kk + 1]);
    u64p s2 = add2(add2(p2[0], p2[1]), add2(p2[2], p2[3]));
    float sl, sh; upk2(s2, sl, sh);
    r = rcpf(sl + sh);
}

// ---------------------------------------------------------------------------
// Stage issue: thread 0 prefetches stage s of this chunk into buffer bufi
// ---------------------------------------------------------------------------
__device__ __forceinline__ void issue_stage(const float4* pf, int c0, int nf4, int s,
                                            int bufi, u32 sbase, u32 mbar, u64p pol) {
    int base = s * STG4;
    int n = nf4 - base; if (n > STG4) n = STG4;
    u32 bytes = (u32)n * 16u;
    mbar_expect_tx(mbar, bytes * NF);
    #pragma unroll
    for (int f = 0; f < NF; f++) {
        u32 dst = sbase + (u32)((bufi * NF + f) * STG4) * 16u;
        bulk_g2s(dst, pf + (size_t)f * NP4 + c0 + base, bytes, mbar, pol);
    }
}

// ---------------------------------------------------------------------------
// Accumulation pass: bulk-copy pipeline + softmax + (W, A) partials
// ---------------------------------------------------------------------------
__global__ __launch_bounds__(256, 1) void pass_acc_kernel(const float* __restrict__ feat,
                                                          int do_update) {
    extern __shared__ char smx[];
    int b = blockIdx.x / NCH;
    int ch = blockIdx.x % NCH;
    int t = threadIdx.x;
    u32 sbase = smem_u32(smx);
    u32 mb = sbase + MBAR_O;
    float* s_g = (float*)(smx + GH_O);
    float* s_h = s_g + NK * NF;
    float4* sbuf = (float4*)smx;

    compute_gh(b, do_update, s_g, s_h);
    if (t == 0) {
        #pragma unroll
        for (int i = 0; i < NBUF; i++) mbar_init(mb + i * 8, 1);
    }
    __syncthreads();

    int c0 = ch * NP4 / NCH;
    int c1 = (ch + 1) * NP4 / NCH;
    int nf4 = c1 - c0;
    int nst = (nf4 + STG4 - 1) / STG4;
    const float4* pf = (const float4*)(feat + (size_t)b * NF * NPIX);
    u64p pol = mk_policy();

    if (t == 0) {
        int pre = nst < NBUF ? nst : NBUF;
        for (int s = 0; s < pre; s++) issue_stage(pf, c0, nf4, s, s, sbase, mb + s * 8, pol);
    }

    u64p g2[NKK][NF], h2[NKK];
    #pragma unroll
    for (int kk = 0; kk < NKK; kk++) {
        h2[kk] = pk2(s_h[2 * kk], s_h[2 * kk + 1]);
        #pragma unroll
        for (int f = 0; f < NF; f++)
            g2[kk][f] = pk2(s_g[(2 * kk) * NF + f], s_g[(2 * kk + 1) * NF + f]);
    }
    u64p aW2[NKK], aA2[NKK][NF];
    #pragma unroll
    for (int kk = 0; kk < NKK; kk++) {
        aW2[kk] = pk2(0.f, 0.f);
        #pragma unroll
        for (int f = 0; f < NF; f++) aA2[kk][f] = pk2(0.f, 0.f);
    }

    for (int s = 0; s < nst; s++) {
        int bufi = s % NBUF;
        u32 ph = (u32)((s / NBUF) & 1);
        mbar_wait(mb + bufi * 8, ph);
        int n = nf4 - s * STG4; if (n > STG4) n = STG4;
        const float4* bp = sbuf + bufi * NF * STG4;
        #pragma unroll
        for (int rep = 0; rep < 2; rep++) {
            int idx = t + rep * 256;
            if (idx < n) {
                float4 u[NF];
                #pragma unroll
                for (int f = 0; f < NF; f++) u[f] = bp[f * STG4 + idx];
                #pragma unroll
                for (int j = 0; j < 4; j++) {
                    float x[NF];
                    #pragma unroll
                    for (int f = 0; f < NF; f++)
                        x[f] = (j == 0) ? u[f].x : ((j == 1) ? u[f].y : ((j == 2) ? u[f].z : u[f].w));
                    u64p x2[NF], p2[NKK]; float r;
                    softmax_core(x, g2, h2, x2, p2, r);
                    u64p r2 = pk2(r, r);
                    #pragma unroll
                    for (int kk = 0; kk < NKK; kk++) {
                        u64p q2 = mul2(p2[kk], r2);
                        aW2[kk] = add2(aW2[kk], q2);
                        #pragma unroll
                        for (int f = 0; f < NF; f++)
                            aA2[kk][f] = fma2(q2, x2[f], aA2[kk][f]);
                    }
                }
            }
        }
        __syncthreads();   // all readers done with buffer bufi
        if (t == 0 && s + NBUF < nst)
            issue_stage(pf, c0, nf4, s + NBUF, bufi, sbase, mb + bufi * 8, pol);
    }

    // Unpack accumulators, then deterministic block reduction
    float aW[NK], aA[NK][NF];
    #pragma unroll
    for (int kk = 0; kk < NKK; kk++) {
        upk2(aW2[kk], aW[2 * kk], aW[2 * kk + 1]);
        #pragma unroll
        for (int f = 0; f < NF; f++)
            upk2(aA2[kk][f], aA[2 * kk][f], aA[2 * kk + 1][f]);
    }
    float (*smr)[NSLOT] = (float (*)[NSLOT])(smx + RED_O);
    int w = t >> 5, lane = t & 31;
    #pragma unroll
    for (int k = 0; k < NK; k++) {
        #pragma unroll
        for (int f = 0; f < NF; f++) {
            float v = aA[k][f];
            #pragma unroll
            for (int o = 16; o; o >>= 1) v += __shfl_xor_sync(0xffffffffu, v, o);
            if (lane == 0) smr[w][k * NF + f] = v;
        }
        float v = aW[k];
        #pragma unroll
        for (int o = 16; o; o >>= 1) v += __shfl_xor_sync(0xffffffffu, v, o);
        if (lane == 0) smr[w][48 + k] = v;
    }
    __syncthreads();
    if (t < NSLOT) {
        float v = 0.f;
        #pragma unroll
        for (int i = 0; i < 8; i++) v += smr[i][t];
        d_part[(size_t)(b * NCH + ch) * NSLOT + t] = v;
    }
}

// ---------------------------------------------------------------------------
// Final pass: pipeline + softmax + write normalized S
// ---------------------------------------------------------------------------
__global__ __launch_bounds__(256, 1) void pass_out_kernel(const float* __restrict__ feat,
                                                          float* __restrict__ out) {
    extern __shared__ char smx[];
    int b = blockIdx.x / NCH;
    int ch = blockIdx.x % NCH;
    int t = threadIdx.x;
    u32 sbase = smem_u32(smx);
    u32 mb = sbase + MBAR_O;
    float* s_g = (float*)(smx + GH_O);
    float* s_h = s_g + NK * NF;
    float4* sbuf = (float4*)smx;

    compute_gh(b, 1, s_g, s_h);
    if (t == 0) {
        #pragma unroll
        for (int i = 0; i < NBUF; i++) mbar_init(mb + i * 8, 1);
    }
    __syncthreads();

    int c0 = ch * NP4 / NCH;
    int c1 = (ch + 1) * NP4 / NCH;
    int nf4 = c1 - c0;
    int nst = (nf4 + STG4 - 1) / STG4;
    const float4* pf = (const float4*)(feat + (size_t)b * NF * NPIX);
    float4* po = (float4*)out + (size_t)b * NK * NP4;
    u64p pol = mk_policy();

    if (t == 0) {
        int pre = nst < NBUF ? nst : NBUF;
        for (int s = 0; s < pre; s++) issue_stage(pf, c0, nf4, s, s, sbase, mb + s * 8, pol);
    }

    u64p g2[NKK][NF], h2[NKK];
    #pragma unroll
    for (int kk = 0; kk < NKK; kk++) {
        h2[kk] = pk2(s_h[2 * kk], s_h[2 * kk + 1]);
        #pragma unroll
        for (int f = 0; f < NF; f++)
            g2[kk][f] = pk2(s_g[(2 * kk) * NF + f], s_g[(2 * kk + 1) * NF + f]);
    }

    for (int s = 0; s < nst; s++) {
        int bufi = s % NBUF;
        u32 ph = (u32)((s / NBUF) & 1);
        mbar_wait(mb + bufi * 8, ph);
        int n = nf4 - s * STG4; if (n > STG4) n = STG4;
        const float4* bp = sbuf + bufi * NF * STG4;
        #pragma unroll
        for (int rep = 0; rep < 2; rep++) {
            int idx = t + rep * 256;
            if (idx < n) {
                float4 u[NF];
                #pragma unroll
                for (int f = 0; f < NF; f++) u[f] = bp[f * STG4 + idx];
                float wv[NK][4];
                #pragma unroll
                for (int j = 0; j < 4; j++) {
                    float x[NF];
                    #pragma unroll
                    for (int f = 0; f < NF; f++)
                        x[f] = (j == 0) ? u[f].x : ((j == 1) ? u[f].y : ((j == 2) ? u[f].z : u[f].w));
                    u64p x2[NF], p2[NKK]; float r;
                    softmax_core(x, g2, h2, x2, p2, r);
                    u64p r2 = pk2(r, r);
                    #pragma unroll
                    for (int kk = 0; kk < NKK; kk++) {
                        u64p w2 = mul2(p2[kk], r2);
                        upk2(w2, wv[2 * kk][j], wv[2 * kk + 1][j]);
                    }
                }
                int gi = c0 + s * STG4 + idx;
                #pragma unroll
                for (int k = 0; k < NK; k++) {
                    float4 o4 = make_float4(wv[k][0], wv[k][1], wv[k][2], wv[k][3]);
                    __stcs(po + k * NP4 + gi, o4);   // streaming: don't evict feat from L2
                }
            }
        }
        __syncthreads();
        if (t == 0 && s + NBUF < nst)
            issue_stage(pf, c0, nf4, s + NBUF, bufi, sbase, mb + bufi * 8, pol);
    }
}

extern "C" void kernel_launch(void* const* d_in, const int* in_sizes, int n_in,
                              void* d_out, int out_size) {
    const float* feat = (const float*)d_in[0];
    const int* idx = (const int*)d_in[1];
    float* out = (float*)d_out;

    cudaFuncSetAttribute(pass_acc_kernel, cudaFuncAttributeMaxDynamicSharedMemorySize, SMEMSZ);
    cudaFuncSetAttribute(pass_out_kernel, cudaFuncAttributeMaxDynamicSharedMemorySize, SMEMSZ);

    stats_kernel<<<NB * NF * SPLIT, 256>>>(feat);
    init_kernel<<<1, 128>>>(feat, idx);
    pass_acc_kernel<<<NB * NCH, 256, SMEMSZ>>>(feat, 0);        // iter 1: init g,h
    for (int i = 1; i < NITERS - 1; i++)
        pass_acc_kernel<<<NB * NCH, 256, SMEMSZ>>>(feat, 1);    // iters 2..11
    pass_out_kernel<<<NB * NCH, 256, SMEMSZ>>>(feat, out);      // iter 12 + output
}